// round 3
// baseline (speedup 1.0000x reference)
#include <cuda_runtime.h>
#include <cuda_bf16.h>

typedef unsigned long long ull;

// Packed f32x2 helpers (Blackwell sm_100a+). ptxas will not auto-generate these.
#define PACK2(d, lo, hi)   asm("mov.b64 %0, {%1, %2};" : "=l"(d) : "f"(lo), "f"(hi))
#define UNPACK2(lo, hi, s) asm("mov.b64 {%0, %1}, %2;" : "=f"(lo), "=f"(hi) : "l"(s))
#define FMA2(d, a, b, c)   asm("fma.rn.f32x2 %0, %1, %2, %3;" : "=l"(d) : "l"(a), "l"(b), "l"(c))
#define ADD2(d, a, b)      asm("add.rn.f32x2 %0, %1, %2;" : "=l"(d) : "l"(a), "l"(b))
#define EX2F(d, s)         asm("ex2.approx.f32 %0, %1;" : "=f"(d) : "f"(s))

// Problem constants
#define BATCH 4
#define CIN   64
#define HNUM  96
#define WNUM  96
#define G     8
#define OG    8
#define IG    8
#define KW    7
#define PAD   3
#define PLANE (HNUM * WNUM)

// Tiling: 192 threads = 12 rows x 16 thread-cols, 2 adjacent pixels per thread.
#define TH 12
#define TW 32
#define TC 16
#define NTHREADS 192
#define HH  (TH + KW - 1)   // 18
#define HWD (TW + KW - 1)   // 38
#define RSTR 40             // padded row stride (floats)

__shared__ float k_s[OG][HH][RSTR];      // 23.0 KB
__shared__ float v_s[OG][HH][RSTR];      // 23.0 KB
__shared__ float  wq_s[OG * IG];
__shared__ float2 wkv_s[OG * IG];        // (wk, wv) interleaved for packed conv
__shared__ float he_s[(OG / 2) * KW];
__shared__ float we_s[(OG / 2) * KW];

__device__ __forceinline__ ull ld2(const float* p) {
    return *(const ull*)p;               // aligned LDS.64 -> pre-packed f32x2 pair
}

// Attention for one channel, one pixel pair. ROWEMB: emb indexed by di (rows);
// else by dj (cols). qep: 7 packed (q0*e, q1*e) values.
template <bool ROWEMB>
__device__ __forceinline__ float2 attn_channel(int c, int y_, int x_,
                                               ull qsp, const ull* qep)
{
    ull ssump = 0ull, accp = 0ull;       // packed (0.f, 0.f)
    #pragma unroll
    for (int di = 0; di < KW; di++) {
        const float* kr = &k_s[c][y_ + di][x_];
        const float* vr = &v_s[c][y_ + di][x_];
        ull kev[4] = { ld2(kr), ld2(kr + 2), ld2(kr + 4), ld2(kr + 6) };
        ull vev[4] = { ld2(vr), ld2(vr + 2), ld2(vr + 4), ld2(vr + 6) };
        float kf[8], vf[8];
        #pragma unroll
        for (int j = 0; j < 4; j++) {
            UNPACK2(kf[2 * j], kf[2 * j + 1], kev[j]);   // register renames
            UNPACK2(vf[2 * j], vf[2 * j + 1], vev[j]);
        }
        ull kod[3], vod[3];
        #pragma unroll
        for (int j = 0; j < 3; j++) {                    // odd-dj pairs
            PACK2(kod[j], kf[2 * j + 1], kf[2 * j + 2]);
            PACK2(vod[j], vf[2 * j + 1], vf[2 * j + 2]);
        }
        #pragma unroll
        for (int dj = 0; dj < KW; dj++) {
            ull kk = (dj & 1) ? kod[dj >> 1] : kev[dj >> 1];
            ull vv = (dj & 1) ? vod[dj >> 1] : vev[dj >> 1];
            ull qe = ROWEMB ? qep[di] : qep[dj];
            ull lp;
            FMA2(lp, qsp, kk, qe);
            float l0, l1;
            UNPACK2(l0, l1, lp);
            float e0, e1;
            EX2F(e0, l0);
            EX2F(e1, l1);
            ull ep;
            PACK2(ep, e0, e1);
            ADD2(ssump, ssump, ep);
            FMA2(accp, ep, vv, accp);
        }
    }
    float s0, s1, a0, a1;
    UNPACK2(s0, s1, ssump);
    UNPACK2(a0, a1, accp);
    return make_float2(__fdividef(a0, s0), __fdividef(a1, s1));
}

__global__ __launch_bounds__(NTHREADS)
void attn_fused_kernel(const float* __restrict__ x,
                       const float* __restrict__ wq,
                       const float* __restrict__ wk,
                       const float* __restrict__ wv,
                       const float* __restrict__ h_emb,
                       const float* __restrict__ w_emb,
                       float* __restrict__ out)
{
    const int tid = threadIdx.x;
    const int bz  = blockIdx.z;          // b*G + g
    const int b   = bz >> 3;
    const int g   = bz & 7;
    const int h0  = blockIdx.y * TH;
    const int w0  = blockIdx.x * TW;

    if (tid < 64) {
        wq_s[tid]  = wq[g * 64 + tid];
        wkv_s[tid] = make_float2(wk[g * 64 + tid], wv[g * 64 + tid]);
    } else if (tid >= 64 && tid < 92) {
        he_s[tid - 64] = h_emb[g * 28 + (tid - 64)];
    } else if (tid >= 96 && tid < 124) {
        we_s[tid - 96] = w_emb[g * 28 + (tid - 96)];
    }
    __syncthreads();

    const float* xg = x + (size_t)(b * CIN + g * IG) * PLANE;

    // --- phase 1: grouped 1x1 conv k,v over haloed tile (packed k/v accum) ---
    for (int p = tid; p < HH * HWD; p += NTHREADS) {
        const int yy = p / HWD;
        const int xx = p - yy * HWD;
        const int gy = h0 + yy - PAD;
        const int gx = w0 + xx - PAD;
        const bool inb = ((unsigned)gy < HNUM) & ((unsigned)gx < WNUM);
        const float* xb = xg + gy * WNUM + gx;
        ull xp[IG];
        #pragma unroll
        for (int i = 0; i < IG; i++) {
            float xi = inb ? __ldg(xb + i * PLANE) : 0.0f;
            PACK2(xp[i], xi, xi);
        }
        #pragma unroll
        for (int c = 0; c < OG; c++) {
            ull kv = 0ull;
            #pragma unroll
            for (int i = 0; i < IG; i++)
                FMA2(kv, xp[i], *(const ull*)&wkv_s[c * IG + i], kv);
            float kc, vc;
            UNPACK2(kc, vc, kv);
            k_s[c][yy][xx] = kc;
            v_s[c][yy][xx] = vc;
        }
    }
    __syncthreads();

    // --- phase 2: attention; each thread owns 2 adjacent pixels, 8 channels ---
    const int tc = tid & (TC - 1);
    const int y_ = tid >> 4;
    const int x_ = 2 * tc;
    const int gh = h0 + y_;
    const int gw = w0 + x_;

    const float LOG2E = 1.4426950408889634f;

    // Precompute packed q (scaled by log2e) for all 8 channels, then drop xi.
    ull qsp[OG];
    {
        float xi0[IG], xi1[IG];
        const float* xb = xg + gh * WNUM + gw;
        #pragma unroll
        for (int i = 0; i < IG; i++) {
            float2 t = __ldg((const float2*)(xb + i * PLANE));
            xi0[i] = t.x; xi1[i] = t.y;
        }
        #pragma unroll
        for (int c = 0; c < OG; c++) {
            float q0 = 0.0f, q1 = 0.0f;
            #pragma unroll
            for (int i = 0; i < IG; i++) {
                q0 = fmaf(wq_s[c * IG + i], xi0[i], q0);
                q1 = fmaf(wq_s[c * IG + i], xi1[i], q1);
            }
            PACK2(qsp[c], q0 * LOG2E, q1 * LOG2E);
        }
    }

    float* op = out + ((size_t)(b * CIN + g * OG) * HNUM + gh) * WNUM + gw;

    // channels 0..3: emb varies along patch ROW (di)
    #pragma unroll 1
    for (int c = 0; c < OG / 2; c++) {
        float q0, q1;
        UNPACK2(q0, q1, qsp[c]);
        ull qep[KW];
        #pragma unroll
        for (int t = 0; t < KW; t++) {
            const float e = he_s[c * KW + t];
            PACK2(qep[t], q0 * e, q1 * e);
        }
        float2 o = attn_channel<true>(c, y_, x_, qsp[c], qep);
        *(float2*)&op[(size_t)c * PLANE] = o;
    }

    // channels 4..7: emb varies along patch COL (dj)
    #pragma unroll 1
    for (int c = OG / 2; c < OG; c++) {
        float q0, q1;
        UNPACK2(q0, q1, qsp[c]);
        ull qep[KW];
        #pragma unroll
        for (int t = 0; t < KW; t++) {
            const float e = we_s[(c - OG / 2) * KW + t];
            PACK2(qep[t], q0 * e, q1 * e);
        }
        float2 o = attn_channel<false>(c, y_, x_, qsp[c], qep);
        *(float2*)&op[(size_t)c * PLANE] = o;
    }
}

extern "C" void kernel_launch(void* const* d_in, const int* in_sizes, int n_in,
                              void* d_out, int out_size)
{
    const float* x     = (const float*)d_in[0];
    const float* wq    = (const float*)d_in[1];
    const float* wk    = (const float*)d_in[2];
    const float* wv    = (const float*)d_in[3];
    const float* h_emb = (const float*)d_in[4];
    const float* w_emb = (const float*)d_in[5];
    float* out = (float*)d_out;

    dim3 grid(WNUM / TW, HNUM / TH, BATCH * G);  // (1, 8, 32)
    dim3 block(NTHREADS);
    attn_fused_kernel<<<grid, block>>>(x, wq, wk, wv, h_emb, w_emb, out);
}

// round 4
// speedup vs baseline: 1.0853x; 1.0853x over previous
#include <cuda_runtime.h>
#include <cuda_bf16.h>

// Problem constants (fixed shapes)
#define BATCH 4
#define CIN   64
#define HNUM  96
#define WNUM  96
#define G     8
#define OG    8
#define OGH   4            // channels handled per block (half of a group)
#define IG    8
#define KW    7
#define PAD   3
#define PLANE (HNUM * WNUM)

// Tiling: 192 threads = 12 rows x 16 thread-cols, 2 adjacent pixels per thread.
#define TH 12
#define TW 32
#define TC 16
#define NTHREADS 192
#define HH  (TH + KW - 1)   // 18
#define HWD (TW + KW - 1)   // 38
#define KVSTR 80            // floats per row: 38 px * 2 (k,v interleaved), pad to 80

__global__ __launch_bounds__(NTHREADS)
void attn_fused_kernel(const float* __restrict__ x,
                       const float* __restrict__ wq,
                       const float* __restrict__ wk,
                       const float* __restrict__ wv,
                       const float* __restrict__ h_emb,
                       const float* __restrict__ w_emb,
                       float* __restrict__ out)
{
    // k,v interleaved per pixel for LDS.128: [ch][row][2*col + {k,v}]
    __shared__ __align__(16) float kv_s[OGH][HH][KVSTR];   // 4*18*80*4 = 22.5 KB
    __shared__ float  wq_s[OGH * IG];
    __shared__ float2 wkv_s[OGH * IG];                     // (wk, wv) pairs
    __shared__ float  emb_s[OGH * KW];                     // h_emb or w_emb slice

    const int tid  = threadIdx.x;
    const int bz   = blockIdx.z;       // ((b*8+g)*2 + half)
    const int half = bz & 1;
    const int g    = (bz >> 1) & 7;
    const int b    = bz >> 4;
    const int h0   = blockIdx.y * TH;
    const int w0   = blockIdx.x * TW;

    // --- per-block weights + embeddings (4 channels worth) ---
    if (tid < 32) {
        const int wi = g * 64 + half * 32 + tid;
        wq_s[tid]  = wq[wi];
        wkv_s[tid] = make_float2(wk[wi], wv[wi]);
    } else if (tid >= 32 && tid < 60) {
        const float* ep = half ? w_emb : h_emb;
        emb_s[tid - 32] = ep[g * 28 + (tid - 32)];
    }
    __syncthreads();

    const float* xg = x + (size_t)(b * CIN + g * IG) * PLANE;
    const int cbase = half * OGH;      // first global channel of this block

    // --- phase 1: grouped 1x1 conv k,v over haloed tile -> interleaved SMEM ---
    for (int p = tid; p < HH * HWD; p += NTHREADS) {
        const int yy = p / HWD;
        const int xx = p - yy * HWD;
        const int gy = h0 + yy - PAD;
        const int gx = w0 + xx - PAD;
        const bool inb = ((unsigned)gy < HNUM) & ((unsigned)gx < WNUM);
        const float* xb = xg + gy * WNUM + gx;
        float xi[IG];
        #pragma unroll
        for (int i = 0; i < IG; i++)
            xi[i] = inb ? __ldg(xb + i * PLANE) : 0.0f;
        #pragma unroll
        for (int c = 0; c < OGH; c++) {
            float kc = 0.0f, vc = 0.0f;
            #pragma unroll
            for (int i = 0; i < IG; i++) {
                const float2 w2 = wkv_s[c * IG + i];
                kc = fmaf(w2.x, xi[i], kc);
                vc = fmaf(w2.y, xi[i], vc);
            }
            *(float2*)&kv_s[c][yy][2 * xx] = make_float2(kc, vc);
        }
    }
    __syncthreads();

    // --- phase 2: attention; each thread owns 2 adjacent pixels, 4 channels ---
    const int tc = tid & (TC - 1);
    const int y_ = tid >> 4;
    const int x_ = 2 * tc;
    const int gh = h0 + y_;
    const int gw = w0 + x_;

    float xi0[IG], xi1[IG];
    {
        const float* xb = xg + gh * WNUM + gw;
        #pragma unroll
        for (int i = 0; i < IG; i++) {
            float2 t = __ldg((const float2*)(xb + i * PLANE));
            xi0[i] = t.x; xi1[i] = t.y;
        }
    }

    float* op = out + ((size_t)(b * CIN + g * OG + cbase) * HNUM + gh) * WNUM + gw;

    const float LOG2E = 1.4426950408889634f;

    if (half == 0) {
        // channels 0..3: emb varies along patch ROW (di)
        #pragma unroll 1
        for (int c = 0; c < OGH; c++) {
            float qs0 = 0.0f, qs1 = 0.0f;
            #pragma unroll
            for (int i = 0; i < IG; i++) {
                qs0 = fmaf(wq_s[c * IG + i], xi0[i], qs0);
                qs1 = fmaf(wq_s[c * IG + i], xi1[i], qs1);
            }
            qs0 *= LOG2E; qs1 *= LOG2E;

            float ssum0 = 0.0f, acc0 = 0.0f, ssum1 = 0.0f, acc1 = 0.0f;
            #pragma unroll
            for (int di = 0; di < KW; di++) {
                const float eh = emb_s[c * KW + di];
                const float qe0 = qs0 * eh, qe1 = qs1 * eh;
                const float4* rp = (const float4*)&kv_s[c][y_ + di][2 * x_];
                float4 a0 = rp[0], a1 = rp[1], a2 = rp[2], a3 = rp[3];
                float kk[8] = {a0.x, a0.z, a1.x, a1.z, a2.x, a2.z, a3.x, a3.z};
                float vv[8] = {a0.y, a0.w, a1.y, a1.w, a2.y, a2.w, a3.y, a3.w};
                #pragma unroll
                for (int dj = 0; dj < KW; dj++) {
                    float e0;
                    asm("ex2.approx.f32 %0, %1;" : "=f"(e0) : "f"(fmaf(qs0, kk[dj], qe0)));
                    ssum0 += e0; acc0 = fmaf(e0, vv[dj], acc0);
                    float e1;
                    asm("ex2.approx.f32 %0, %1;" : "=f"(e1) : "f"(fmaf(qs1, kk[dj + 1], qe1)));
                    ssum1 += e1; acc1 = fmaf(e1, vv[dj + 1], acc1);
                }
            }
            float2 o = make_float2(__fdividef(acc0, ssum0), __fdividef(acc1, ssum1));
            *(float2*)&op[(size_t)c * PLANE] = o;
        }
    } else {
        // channels 4..7: emb varies along patch COL (dj)
        #pragma unroll 1
        for (int c = 0; c < OGH; c++) {
            float qs0 = 0.0f, qs1 = 0.0f;
            #pragma unroll
            for (int i = 0; i < IG; i++) {
                qs0 = fmaf(wq_s[c * IG + i], xi0[i], qs0);
                qs1 = fmaf(wq_s[c * IG + i], xi1[i], qs1);
            }
            qs0 *= LOG2E; qs1 *= LOG2E;

            float qe0a[KW], qe1a[KW];
            #pragma unroll
            for (int t = 0; t < KW; t++) {
                const float ew = emb_s[c * KW + t];
                qe0a[t] = qs0 * ew;
                qe1a[t] = qs1 * ew;
            }

            float ssum0 = 0.0f, acc0 = 0.0f, ssum1 = 0.0f, acc1 = 0.0f;
            #pragma unroll
            for (int di = 0; di < KW; di++) {
                const float4* rp = (const float4*)&kv_s[c][y_ + di][2 * x_];
                float4 a0 = rp[0], a1 = rp[1], a2 = rp[2], a3 = rp[3];
                float kk[8] = {a0.x, a0.z, a1.x, a1.z, a2.x, a2.z, a3.x, a3.z};
                float vv[8] = {a0.y, a0.w, a1.y, a1.w, a2.y, a2.w, a3.y, a3.w};
                #pragma unroll
                for (int dj = 0; dj < KW; dj++) {
                    float e0;
                    asm("ex2.approx.f32 %0, %1;" : "=f"(e0) : "f"(fmaf(qs0, kk[dj], qe0a[dj])));
                    ssum0 += e0; acc0 = fmaf(e0, vv[dj], acc0);
                    float e1;
                    asm("ex2.approx.f32 %0, %1;" : "=f"(e1) : "f"(fmaf(qs1, kk[dj + 1], qe1a[dj])));
                    ssum1 += e1; acc1 = fmaf(e1, vv[dj + 1], acc1);
                }
            }
            float2 o = make_float2(__fdividef(acc0, ssum0), __fdividef(acc1, ssum1));
            *(float2*)&op[(size_t)c * PLANE] = o;
        }
    }
}

extern "C" void kernel_launch(void* const* d_in, const int* in_sizes, int n_in,
                              void* d_out, int out_size)
{
    const float* x     = (const float*)d_in[0];
    const float* wq    = (const float*)d_in[1];
    const float* wk    = (const float*)d_in[2];
    const float* wv    = (const float*)d_in[3];
    const float* h_emb = (const float*)d_in[4];
    const float* w_emb = (const float*)d_in[5];
    float* out = (float*)d_out;

    dim3 grid(WNUM / TW, HNUM / TH, BATCH * G * 2);  // (3, 8, 64) = 1536 blocks
    dim3 block(NTHREADS);
    attn_fused_kernel<<<grid, block>>>(x, wq, wk, wv, h_emb, w_emb, out);
}